// round 5
// baseline (speedup 1.0000x reference)
#include <cuda_runtime.h>
#include <math.h>

#define NLVL 4
#define HD   1024
#define SEQ  512
#define NBLK 128
#define NTHR 256
#define NWARP 8

// ---------------- device scratch (static, no allocation) ----------------
__device__ __align__(16) float G_gelu0[SEQ * HD];   // gelu(ew1_0 @ x_t + eb1_0), all t
__device__ __align__(16) float G_enc0 [SEQ * HD];   // enc level0, all t  (const in main)
__device__ __align__(16) float G_pe0  [SEQ * HD];   // enc0 * prec0, all t (const in main)
__device__ float G_fe0[SEQ];                        // per-t fe contribution level0
__device__ __align__(16) float G_h    [3 * HD];     // h0,h1,h2 (h3 provably dead)
__device__ __align__(16) float G_gates[3 * HD];     // i,g,o pre-activations (current)
__device__ __align__(16) float G_z1   [HD];         // pw1 outputs
__device__ __align__(16) float G_z2   [HD];         // ew1 outputs
__device__ __align__(16) float G_pred [NLVL * HD];  // per-level pred (levels 1..3)
__device__ __align__(16) float G_encL [NLVL * HD];  // per-level enc (levels 1..3)
__device__ float G_scal[NLVL];                      // err.qw + qb per level
__device__ unsigned g_arrive;

// ---------------- helpers ----------------
__device__ __forceinline__ float gelu_f(float x) {
    return 0.5f * x * (1.0f + erff(x * 0.7071067811865475f));
}
__device__ __forceinline__ float sigm(float x) {
    return 1.0f / (1.0f + __expf(-x));
}

// grid-wide barrier: single counter, native release/acquire semantics.
// Each arriving block performs a RELEASE RMW; pollers use ACQUIRE loads.
// The RMW release-sequence on one location makes every arriver's prior
// writes visible to every block that observes count >= e*NBLK.
__device__ __forceinline__ void gsync(unsigned e) {
    __syncthreads();
    if (threadIdx.x == 0) {
        const unsigned target = e * NBLK;
        asm volatile("red.release.gpu.add.u32 [%0], %1;"
                     :: "l"(&g_arrive), "r"(1u) : "memory");
        unsigned v;
        do {
            asm volatile("ld.acquire.gpu.u32 %0, [%1];"
                         : "=r"(v) : "l"(&g_arrive) : "memory");
        } while (v < target);
    }
    __syncthreads();
}

// block reduce; result valid in thread 0
__device__ __forceinline__ float block_reduce(float v, float* sred) {
#pragma unroll
    for (int o = 16; o; o >>= 1) v += __shfl_xor_sync(0xffffffffu, v, o);
    int w = threadIdx.x >> 5;
    if ((threadIdx.x & 31) == 0) sred[w] = v;
    __syncthreads();
    if (threadIdx.x < 32) {
        v = (threadIdx.x < NWARP) ? sred[threadIdx.x] : 0.0f;
#pragma unroll
        for (int o = 4; o; o >>= 1) v += __shfl_xor_sync(0xffffffffu, v, o);
    }
    __syncthreads();
    return v;
}

// load smem x vector (1024 floats) into 8 float4 registers for this lane
__device__ __forceinline__ void load_xr(const float* sx, int lane, float4* xr) {
    const float4* p = (const float4*)sx;
#pragma unroll
    for (int k = 0; k < 8; k++) xr[k] = p[lane + 32 * k];
}

// one warp computes dot(W_row, x) with x in registers, reduced across warp
__device__ __forceinline__ float dot_row(const float* __restrict__ Wrow,
                                         const float4* xr, int lane) {
    const float4* w4 = (const float4*)Wrow;
    float acc = 0.0f;
#pragma unroll
    for (int k = 0; k < 8; k++) {
        float4 w = w4[lane + 32 * k];
        acc = fmaf(w.x, xr[k].x, acc);
        acc = fmaf(w.y, xr[k].y, acc);
        acc = fmaf(w.z, xr[k].z, acc);
        acc = fmaf(w.w, xr[k].w, acc);
    }
#pragma unroll
    for (int o = 16; o; o >>= 1) acc += __shfl_xor_sync(0xffffffffu, acc, o);
    return acc;
}

// ---------------- init ----------------
__global__ void init_kernel() {
    int i = blockIdx.x * blockDim.x + threadIdx.x;
    if (i < 3 * HD) G_h[i] = 0.0f;
    if (i == 0) g_arrive = 0u;
}

// ---------------- level-0 precompute (proven in round 4) -----------------
__global__ void __launch_bounds__(NTHR) pre_gelu0(const float* __restrict__ obs,
                                                  const float* __restrict__ ew1,
                                                  const float* __restrict__ eb1) {
    __shared__ __align__(16) float sx[HD];
    const int t = blockIdx.y, tid = threadIdx.x;
    const int lane = tid & 31, wid = tid >> 5;
    const int gw = blockIdx.x * NWARP + wid;
    for (int i = tid; i < HD; i += NTHR) sx[i] = obs[(size_t)t * HD + i];
    __syncthreads();
    float4 xr[8]; load_xr(sx, lane, xr);
    float r = dot_row(ew1 + (size_t)gw * HD, xr, lane);
    if (lane == 0) G_gelu0[(size_t)t * HD + gw] = gelu_f(r + eb1[gw]);
}

__global__ void __launch_bounds__(NTHR) pre_enc0(const float* __restrict__ ew2,
                                                 const float* __restrict__ eb2) {
    __shared__ __align__(16) float sx[HD];
    const int t = blockIdx.y, tid = threadIdx.x;
    const int lane = tid & 31, wid = tid >> 5;
    const int gw = blockIdx.x * NWARP + wid;
    for (int i = tid; i < HD; i += NTHR) sx[i] = G_gelu0[(size_t)t * HD + i];
    __syncthreads();
    float4 xr[8]; load_xr(sx, lane, xr);
    float r = dot_row(ew2 + (size_t)gw * HD, xr, lane);
    if (lane == 0) G_enc0[(size_t)t * HD + gw] = r + eb2[gw];
}

__global__ void __launch_bounds__(NTHR) lvl0_aux(const float* __restrict__ obs,
                                                 const float* __restrict__ qw,
                                                 const float* __restrict__ qb) {
    __shared__ float sred[NWARP];
    __shared__ float sprec;
    const int t = blockIdx.x, tid = threadIdx.x;
    float d = 0.0f;
    for (int i = tid; i < HD; i += NTHR)
        d = fmaf(obs[(size_t)t * HD + i], qw[i], d);   // err0 = x_t (pred0 == 0)
    d = block_reduce(d, sred);
    if (tid == 0) sprec = sigm(d + qb[0]);
    __syncthreads();
    float prec = sprec, s = 0.0f;
    for (int i = tid; i < HD; i += NTHR) {
        float e = G_enc0[(size_t)t * HD + i];
        G_pe0[(size_t)t * HD + i] = e * prec;
        s = fmaf(e, e, s);
    }
    s = block_reduce(s, sred);
    if (tid == 0) G_fe0[t] = s * prec;
}

// ---------------- persistent main kernel (round-4 phase bodies) ----------
__global__ void __launch_bounds__(NTHR, 1) main_kernel(
    const float* __restrict__ pw1, const float* __restrict__ pb1,
    const float* __restrict__ pw2, const float* __restrict__ pb2,
    const float* __restrict__ ew1, const float* __restrict__ eb1,
    const float* __restrict__ ew2, const float* __restrict__ eb2,
    const float* __restrict__ qw,  const float* __restrict__ qb,
    const float* __restrict__ wih, const float* __restrict__ bih,
    const float* __restrict__ bhh, float* __restrict__ out) {
    __shared__ __align__(16) float sx[HD];
    __shared__ float sred[NWARP];
    const int tid = threadIdx.x, lane = tid & 31, wid = tid >> 5;
    const int gw = blockIdx.x * NWARP + wid;   // 0..1023, one warp per row
    unsigned epoch = 0;
    float fe_acc = 0.0f;                       // redundant per block; tid0 holds it

    for (int t = 0; t < SEQ; t++) {
        // ===== phase A: deferred fe3(t-1); gates_0 = wih_0 @ (h0 + pe0[t]) =====
        if (t > 0) {
            float p2 = 0.0f;
            for (int i = tid; i < HD; i += NTHR) {
                float e = __ldcg(&G_encL[3 * HD + i]);
                p2 = fmaf(e, e, p2);
            }
            p2 = block_reduce(p2, sred);
            if (tid == 0) fe_acc += p2 * sigm(__ldcg(&G_scal[3]));
        }
        for (int i = tid; i < HD; i += NTHR)
            sx[i] = __ldcg(&G_h[i]) + G_pe0[(size_t)t * HD + i];
        __syncthreads();
        {
            float4 xr[8]; load_xr(sx, lane, xr);
#pragma unroll
            for (int w = 0; w < 3; w++) {
                int lr = gw + w * HD;                 // logical rows: i, g, o
                int ar = (lr < HD) ? lr : lr + HD;    // skip dead forget-gate rows
                float r = dot_row(wih + (size_t)ar * HD, xr, lane);
                if (lane == 0) __stcg(&G_gates[lr], r + bih[ar] + bhh[ar]);
            }
        }
        gsync(++epoch);

        for (int l = 1; l < NLVL; l++) {
            // ===== p1: h_{l-1} = lstm(gates); z1 = pw1_l @ h_{l-1} =====
            for (int i = tid; i < HD; i += NTHR) {
                float zi = __ldcg(&G_gates[i]);
                float zg = __ldcg(&G_gates[HD + i]);
                float zo = __ldcg(&G_gates[2 * HD + i]);
                float hv = sigm(zo) * tanhf(sigm(zi) * tanhf(zg));
                sx[i] = hv;
                if (blockIdx.x == 0) __stcg(&G_h[(size_t)(l - 1) * HD + i], hv);
            }
            __syncthreads();
            {
                float4 xr[8]; load_xr(sx, lane, xr);
                float r = dot_row(pw1 + ((size_t)l * HD + gw) * HD, xr, lane);
                if (lane == 0) __stcg(&G_z1[gw], r + pb1[l * HD + gw]);
            }
            gsync(++epoch);

            // ===== p2: pred_l = pw2_l @ gelu(z1) =====
            for (int i = tid; i < HD; i += NTHR) sx[i] = gelu_f(__ldcg(&G_z1[i]));
            __syncthreads();
            {
                float4 xr[8]; load_xr(sx, lane, xr);
                float r = dot_row(pw2 + ((size_t)l * HD + gw) * HD, xr, lane);
                if (lane == 0) __stcg(&G_pred[l * HD + gw], r + pb2[l * HD + gw]);
            }
            gsync(++epoch);

            // ===== p3: err = enc_{l-1} - pred; scal_l = err.qw+qb; z2 = ew1_l @ err =====
            float part = 0.0f;
            for (int i = tid; i < HD; i += NTHR) {
                float ep = (l == 1) ? G_enc0[(size_t)t * HD + i]
                                    : __ldcg(&G_encL[(size_t)(l - 1) * HD + i]);
                float e = ep - __ldcg(&G_pred[l * HD + i]);
                sx[i] = e;
                part = fmaf(e, qw[l * HD + i], part);
            }
            part = block_reduce(part, sred);
            if (blockIdx.x == 0 && tid == 0) __stcg(&G_scal[l], part + qb[l]);
            __syncthreads();
            {
                float4 xr[8]; load_xr(sx, lane, xr);
                float r = dot_row(ew1 + ((size_t)l * HD + gw) * HD, xr, lane);
                if (lane == 0) __stcg(&G_z2[gw], r + eb1[l * HD + gw]);
            }
            gsync(++epoch);

            // ===== p4: enc_l = ew2_l @ gelu(z2) =====
            for (int i = tid; i < HD; i += NTHR) sx[i] = gelu_f(__ldcg(&G_z2[i]));
            __syncthreads();
            {
                float4 xr[8]; load_xr(sx, lane, xr);
                float r = dot_row(ew2 + ((size_t)l * HD + gw) * HD, xr, lane);
                if (lane == 0) __stcg(&G_encL[l * HD + gw], r + eb2[l * HD + gw]);
            }
            gsync(++epoch);

            // ===== p5 (l<3): gates_l = wih_l @ (h_l + enc_l*prec_l); fe term =====
            if (l < 3) {
                float prec = sigm(__ldcg(&G_scal[l]));
                float p2 = 0.0f;
                for (int i = tid; i < HD; i += NTHR) {
                    float e = __ldcg(&G_encL[l * HD + i]);
                    sx[i] = __ldcg(&G_h[(size_t)l * HD + i]) + e * prec;
                    p2 = fmaf(e, e, p2);
                }
                p2 = block_reduce(p2, sred);
                if (tid == 0) fe_acc += p2 * prec;
                __syncthreads();
                {
                    float4 xr[8]; load_xr(sx, lane, xr);
                    const float* W = wih + (size_t)l * 4 * HD * HD;
#pragma unroll
                    for (int w = 0; w < 3; w++) {
                        int lr = gw + w * HD;
                        int ar = (lr < HD) ? lr : lr + HD;
                        float r = dot_row(W + (size_t)ar * HD, xr, lane);
                        if (lane == 0)
                            __stcg(&G_gates[lr],
                                   r + bih[l * 4 * HD + ar] + bhh[l * 4 * HD + ar]);
                    }
                }
                gsync(++epoch);
            }
        }
    }

    // ===== epilogue (block 0): final fe3; outputs [preds(4H), errs(4H), fe] =====
    if (blockIdx.x == 0) {
        float p2 = 0.0f;
        for (int i = tid; i < HD; i += NTHR) {
            float e = __ldcg(&G_encL[3 * HD + i]);
            p2 = fmaf(e, e, p2);
        }
        p2 = block_reduce(p2, sred);
        float fe3 = p2 * sigm(__ldcg(&G_scal[3]));   // valid in tid 0

        for (int i = tid; i < HD; i += NTHR) {
            out[i] = 0.0f;                                         // pred level 0 == 0
            out[1 * HD + i] = __ldcg(&G_pred[1 * HD + i]);
            out[2 * HD + i] = __ldcg(&G_pred[2 * HD + i]);
            out[3 * HD + i] = __ldcg(&G_pred[3 * HD + i]);
            out[4 * HD + i] = G_enc0[(size_t)(SEQ - 1) * HD + i];  // err level 0 = enc0
            out[5 * HD + i] = __ldcg(&G_encL[1 * HD + i]);
            out[6 * HD + i] = __ldcg(&G_encL[2 * HD + i]);
            out[7 * HD + i] = __ldcg(&G_encL[3 * HD + i]);
        }
        float s = 0.0f;
        for (int i = tid; i < SEQ; i += NTHR) s += G_fe0[i];
        s = block_reduce(s, sred);
        if (tid == 0) out[8 * HD] = s + fe_acc + fe3;
    }
}

// ---------------- launch ----------------
extern "C" void kernel_launch(void* const* d_in, const int* in_sizes, int n_in,
                              void* d_out, int out_size) {
    (void)n_in; (void)out_size;
    const float *obs, *pw1, *pb1, *pw2, *pb2, *ew1, *eb1, *ew2, *eb2;
    const float *qw, *qb, *wih, *bih, *bhh;
    if (in_sizes[0] == SEQ * HD) {
        // dict / signature order
        obs = (const float*)d_in[0];
        pw1 = (const float*)d_in[1];  pb1 = (const float*)d_in[2];
        pw2 = (const float*)d_in[3];  pb2 = (const float*)d_in[4];
        ew1 = (const float*)d_in[5];  eb1 = (const float*)d_in[6];
        ew2 = (const float*)d_in[7];  eb2 = (const float*)d_in[8];
        qw  = (const float*)d_in[9];  qb  = (const float*)d_in[10];
        wih = (const float*)d_in[11]; // d_in[12] = whh unused (h0 == 0 each step)
        bih = (const float*)d_in[13]; bhh = (const float*)d_in[14];
    } else {
        // alphabetical: bhh,bih,eb1,eb2,ew1,ew2,observed,pb1,pb2,pw1,pw2,qb,qw,whh,wih
        bhh = (const float*)d_in[0];  bih = (const float*)d_in[1];
        eb1 = (const float*)d_in[2];  eb2 = (const float*)d_in[3];
        ew1 = (const float*)d_in[4];  ew2 = (const float*)d_in[5];
        obs = (const float*)d_in[6];
        pb1 = (const float*)d_in[7];  pb2 = (const float*)d_in[8];
        pw1 = (const float*)d_in[9];  pw2 = (const float*)d_in[10];
        qb  = (const float*)d_in[11]; qw  = (const float*)d_in[12];
        wih = (const float*)d_in[14]; // d_in[13] = whh unused
    }
    float* out = (float*)d_out;

    init_kernel<<<16, NTHR>>>();
    dim3 gp(NBLK, SEQ);
    pre_gelu0<<<gp, NTHR>>>(obs, ew1, eb1);  // level-0 gelu1, all t
    pre_enc0 <<<gp, NTHR>>>(ew2, eb2);       // level-0 enc, all t
    lvl0_aux <<<SEQ, NTHR>>>(obs, qw, qb);   // prec0 / pe0 / fe0
    main_kernel<<<NBLK, NTHR>>>(pw1, pb1, pw2, pb2, ew1, eb1, ew2, eb2,
                                qw, qb, wih, bih, bhh, out);
}

// round 6
// speedup vs baseline: 2.0613x; 2.0613x over previous
#include <cuda_runtime.h>
#include <math.h>

#define NLVL 4
#define HD   1024
#define SEQ  512
#define NBLK 128
#define NTHR 256
#define NWARP 8
#define TT   8          // timesteps per GEMM block

// ---------------- device scratch (static, no allocation) ----------------
__device__ __align__(16) float B_G   [SEQ * HD];      // gelu intermediate buffer
__device__ __align__(16) float B_ENC0[SEQ * HD];
__device__ __align__(16) float B_ENC1[SEQ * HD];
__device__ __align__(16) float B_ENC2[SEQ * HD];
__device__ __align__(16) float B_ENC3[SEQ * HD];
__device__ __align__(16) float B_P1  [SEQ * HD];
__device__ __align__(16) float B_P2  [SEQ * HD];
__device__ __align__(16) float B_P3  [SEQ * HD];
__device__ __align__(16) float B_H0  [SEQ * HD];
__device__ __align__(16) float B_H1  [SEQ * HD];
__device__ __align__(16) float B_H2  [SEQ * HD];
__device__ __align__(16) float B_PE  [SEQ * HD];      // prec * enc (per level, reused)
__device__ __align__(16) float B_C   [SEQ * 3 * HD];  // gates constant term (reused)
__device__ float B_prec[SEQ];                          // per-t prec of current level
__device__ float B_fe [4 * SEQ];                       // per-level per-t fe terms
__device__ __align__(16) float G_gates[3 * HD];        // chain gates (i,g,o)
__device__ unsigned g_arrive;

// ---------------- helpers ----------------
__device__ __forceinline__ float gelu_f(float x) {
    return 0.5f * x * (1.0f + erff(x * 0.7071067811865475f));
}
__device__ __forceinline__ float sigm(float x) {
    return 1.0f / (1.0f + __expf(-x));
}

// grid-wide barrier (round-5 proven): release RMW + acquire polling, one counter
__device__ __forceinline__ void gsync(unsigned e) {
    __syncthreads();
    if (threadIdx.x == 0) {
        const unsigned target = e * NBLK;
        asm volatile("red.release.gpu.add.u32 [%0], %1;"
                     :: "l"(&g_arrive), "r"(1u) : "memory");
        unsigned v;
        do {
            asm volatile("ld.acquire.gpu.u32 %0, [%1];"
                         : "=r"(v) : "l"(&g_arrive) : "memory");
        } while (v < target);
    }
    __syncthreads();
}

// block reduce; result valid in thread 0
__device__ __forceinline__ float block_reduce(float v, float* sred) {
#pragma unroll
    for (int o = 16; o; o >>= 1) v += __shfl_xor_sync(0xffffffffu, v, o);
    int w = threadIdx.x >> 5;
    if ((threadIdx.x & 31) == 0) sred[w] = v;
    __syncthreads();
    if (threadIdx.x < 32) {
        v = (threadIdx.x < NWARP) ? sred[threadIdx.x] : 0.0f;
#pragma unroll
        for (int o = 4; o; o >>= 1) v += __shfl_xor_sync(0xffffffffu, v, o);
    }
    __syncthreads();
    return v;
}

__device__ __forceinline__ void load_xr(const float* sx, int lane, float4* xr) {
    const float4* p = (const float4*)sx;
#pragma unroll
    for (int k = 0; k < 8; k++) xr[k] = p[lane + 32 * k];
}

__device__ __forceinline__ float dot_row(const float* __restrict__ Wrow,
                                         const float4* xr, int lane) {
    const float4* w4 = (const float4*)Wrow;
    float acc = 0.0f;
#pragma unroll
    for (int k = 0; k < 8; k++) {
        float4 w = w4[lane + 32 * k];
        acc = fmaf(w.x, xr[k].x, acc);
        acc = fmaf(w.y, xr[k].y, acc);
        acc = fmaf(w.z, xr[k].z, acc);
        acc = fmaf(w.w, xr[k].w, acc);
    }
#pragma unroll
    for (int o = 16; o; o >>= 1) acc += __shfl_xor_sync(0xffffffffu, acc, o);
    return acc;
}

// ---------------- init ----------------
__global__ void init_bar() { g_arrive = 0u; }

// ---------------- batched GEMM over timesteps ----------------
// out[t][lr] = act( W[ar] @ x_t + biasA[ar] (+ biasB[ar]) )
// x_t = inA[t] (- inB[t] if inB);  gates mode (out_rows==3*HD): ar skips forget rows
__global__ void __launch_bounds__(NTHR) gemm_k(
    const float* __restrict__ W,
    const float* __restrict__ biasA, const float* __restrict__ biasB,
    const float* __restrict__ inA,  const float* __restrict__ inB,
    float* __restrict__ outp, int out_rows, int out_gelu) {
    __shared__ __align__(16) float sx[TT][HD];
    const int tid = threadIdx.x, lane = tid & 31, wid = tid >> 5;
    const int t0 = blockIdx.y * TT;
    const bool gates = (out_rows == 3 * HD);

    for (int tt = 0; tt < TT; tt++)
        for (int i = tid; i < HD; i += NTHR) {
            float v = inA[(size_t)(t0 + tt) * HD + i];
            if (inB) v -= inB[(size_t)(t0 + tt) * HD + i];
            sx[tt][i] = v;
        }
    __syncthreads();

#pragma unroll
    for (int rr = 0; rr < 2; rr++) {
        const int lr = blockIdx.x * 16 + wid * 2 + rr;
        const int ar = gates ? ((lr < HD) ? lr : lr + HD) : lr;
        const float4* w4 = (const float4*)(W + (size_t)ar * HD);
        float4 wr[8];
#pragma unroll
        for (int k = 0; k < 8; k++) wr[k] = w4[lane + 32 * k];
        float acc[TT];
#pragma unroll
        for (int tt = 0; tt < TT; tt++) {
            const float4* p = (const float4*)sx[tt];
            float a = 0.0f;
#pragma unroll
            for (int k = 0; k < 8; k++) {
                float4 x = p[lane + 32 * k];
                a = fmaf(wr[k].x, x.x, a);
                a = fmaf(wr[k].y, x.y, a);
                a = fmaf(wr[k].z, x.z, a);
                a = fmaf(wr[k].w, x.w, a);
            }
            acc[tt] = a;
        }
#pragma unroll
        for (int tt = 0; tt < TT; tt++)
#pragma unroll
            for (int o = 16; o; o >>= 1)
                acc[tt] += __shfl_xor_sync(0xffffffffu, acc[tt], o);
        if (lane == 0) {
            float b = biasA[ar] + (biasB ? biasB[ar] : 0.0f);
            for (int tt = 0; tt < TT; tt++) {
                float v = acc[tt] + b;
                if (out_gelu) v = gelu_f(v);
                outp[(size_t)(t0 + tt) * out_rows + lr] = v;
            }
        }
    }
}

// ---------------- per-t aux kernels ----------------
// level 0: prec0 from obs (err0 == obs), PE = prec0*enc0, fe0
__global__ void __launch_bounds__(NTHR) lvl0_aux(const float* __restrict__ obs,
                                                 const float* __restrict__ qw,
                                                 const float* __restrict__ qb) {
    __shared__ float sred[NWARP];
    __shared__ float sprec;
    const int t = blockIdx.x, tid = threadIdx.x;
    float d = 0.0f;
    for (int i = tid; i < HD; i += NTHR)
        d = fmaf(obs[(size_t)t * HD + i], qw[i], d);
    d = block_reduce(d, sred);
    if (tid == 0) sprec = sigm(d + qb[0]);
    __syncthreads();
    float prec = sprec, s = 0.0f;
    for (int i = tid; i < HD; i += NTHR) {
        float e = B_ENC0[(size_t)t * HD + i];
        B_PE[(size_t)t * HD + i] = e * prec;
        s = fmaf(e, e, s);
    }
    s = block_reduce(s, sred);
    if (tid == 0) B_fe[t] = s * prec;           // level 0 row
}

// levels 1..3: prec_l(t) = sigm( (encprev - P)·qw_l + qb_l )
__global__ void __launch_bounds__(NTHR) aux_scal(const float* __restrict__ encprev,
                                                 const float* __restrict__ P,
                                                 const float* __restrict__ qwl,
                                                 const float* __restrict__ qb, int l) {
    __shared__ float sred[NWARP];
    const int t = blockIdx.x, tid = threadIdx.x;
    float d = 0.0f;
    for (int i = tid; i < HD; i += NTHR) {
        float e = encprev[(size_t)t * HD + i] - P[(size_t)t * HD + i];
        d = fmaf(e, qwl[i], d);
    }
    d = block_reduce(d, sred);
    if (tid == 0) B_prec[t] = sigm(d + qb[l]);
}

// PE = prec*enc; fe_l(t) = prec * sum(enc^2)
__global__ void __launch_bounds__(NTHR) aux_pe(const float* __restrict__ enc, int l) {
    __shared__ float sred[NWARP];
    const int t = blockIdx.x, tid = threadIdx.x;
    float prec = B_prec[t], s = 0.0f;
    for (int i = tid; i < HD; i += NTHR) {
        float e = enc[(size_t)t * HD + i];
        B_PE[(size_t)t * HD + i] = e * prec;
        s = fmaf(e, e, s);
    }
    s = block_reduce(s, sred);
    if (tid == 0) B_fe[l * SEQ + t] = s * prec;
}

// ---------------- sequential LSTM hidden chain (persistent) ----------------
// gates(t) = wih @ h(t-1) + C(t)   [C includes wih@(prec*enc) + bih + bhh]
// h(t) = sigm(o)*tanh(sigm(i)*tanh(g));  Hout[t] = h(t)
__global__ void __launch_bounds__(NTHR, 1) chain_k(const float* __restrict__ Wih,
                                                   const float* __restrict__ C,
                                                   float* __restrict__ Hout) {
    __shared__ __align__(16) float sx[HD];
    const int tid = threadIdx.x, lane = tid & 31, wid = tid >> 5;
    const int gw = blockIdx.x * NWARP + wid;   // 0..1023
    unsigned epoch = 0;

    for (int t = 0; t < SEQ; t++) {
        if (t > 0) {
            for (int i = tid; i < HD; i += NTHR) {
                float zi = __ldcg(&G_gates[i]);
                float zg = __ldcg(&G_gates[HD + i]);
                float zo = __ldcg(&G_gates[2 * HD + i]);
                float hv = sigm(zo) * tanhf(sigm(zi) * tanhf(zg));
                sx[i] = hv;
                if (blockIdx.x == 0) Hout[(size_t)(t - 1) * HD + i] = hv;
            }
        }
        __syncthreads();
        float4 xr[8];
        if (t > 0) load_xr(sx, lane, xr);
#pragma unroll
        for (int w = 0; w < 3; w++) {
            int lr = gw + w * HD;
            int ar = (lr < HD) ? lr : lr + HD;          // skip forget gate
            float r = C[(size_t)t * 3 * HD + lr];
            if (t > 0) r += dot_row(Wih + (size_t)ar * HD, xr, lane);
            if (lane == 0) __stcg(&G_gates[lr], r);
        }
        gsync(++epoch);
    }
    // final h(SEQ-1)
    if (blockIdx.x == 0) {
        for (int i = tid; i < HD; i += NTHR) {
            float zi = __ldcg(&G_gates[i]);
            float zg = __ldcg(&G_gates[HD + i]);
            float zo = __ldcg(&G_gates[2 * HD + i]);
            Hout[(size_t)(SEQ - 1) * HD + i] =
                sigm(zo) * tanhf(sigm(zi) * tanhf(zg));
        }
    }
}

// ---------------- epilogue ----------------
__global__ void __launch_bounds__(NTHR) k_epi(float* __restrict__ out) {
    __shared__ float sred[NWARP];
    const int tid = threadIdx.x;
    const size_t last = (size_t)(SEQ - 1) * HD;
    for (int i = tid; i < HD; i += NTHR) {
        out[i] = 0.0f;                              // pred level 0 == 0
        out[1 * HD + i] = B_P1[last + i];
        out[2 * HD + i] = B_P2[last + i];
        out[3 * HD + i] = B_P3[last + i];
        out[4 * HD + i] = B_ENC0[last + i];         // err level 0 = enc0
        out[5 * HD + i] = B_ENC1[last + i];
        out[6 * HD + i] = B_ENC2[last + i];
        out[7 * HD + i] = B_ENC3[last + i];
    }
    float s = 0.0f;
    for (int t = tid; t < SEQ; t += NTHR)
        s += B_fe[t] + B_fe[SEQ + t] + B_fe[2 * SEQ + t] + B_fe[3 * SEQ + t];
    s = block_reduce(s, sred);
    if (tid == 0) out[8 * HD] = s;
}

// ---------------- launch ----------------
extern "C" void kernel_launch(void* const* d_in, const int* in_sizes, int n_in,
                              void* d_out, int out_size) {
    (void)n_in; (void)out_size;
    const float *obs, *pw1, *pb1, *pw2, *pb2, *ew1, *eb1, *ew2, *eb2;
    const float *qw, *qb, *wih, *bih, *bhh;
    if (in_sizes[0] == SEQ * HD) {
        obs = (const float*)d_in[0];
        pw1 = (const float*)d_in[1];  pb1 = (const float*)d_in[2];
        pw2 = (const float*)d_in[3];  pb2 = (const float*)d_in[4];
        ew1 = (const float*)d_in[5];  eb1 = (const float*)d_in[6];
        ew2 = (const float*)d_in[7];  eb2 = (const float*)d_in[8];
        qw  = (const float*)d_in[9];  qb  = (const float*)d_in[10];
        wih = (const float*)d_in[11];  // whh unused
        bih = (const float*)d_in[13]; bhh = (const float*)d_in[14];
    } else {
        bhh = (const float*)d_in[0];  bih = (const float*)d_in[1];
        eb1 = (const float*)d_in[2];  eb2 = (const float*)d_in[3];
        ew1 = (const float*)d_in[4];  ew2 = (const float*)d_in[5];
        obs = (const float*)d_in[6];
        pb1 = (const float*)d_in[7];  pb2 = (const float*)d_in[8];
        pw1 = (const float*)d_in[9];  pw2 = (const float*)d_in[10];
        qb  = (const float*)d_in[11]; qw  = (const float*)d_in[12];
        wih = (const float*)d_in[14];  // whh unused
    }
    float* out = (float*)d_out;

    // device-global buffer addresses (pure lookups; capture-safe)
    float *bG, *bE0, *bE1, *bE2, *bE3, *bP1, *bP2, *bP3, *bH0, *bH1, *bH2, *bPE, *bC;
    cudaGetSymbolAddress((void**)&bG,  B_G);
    cudaGetSymbolAddress((void**)&bE0, B_ENC0);
    cudaGetSymbolAddress((void**)&bE1, B_ENC1);
    cudaGetSymbolAddress((void**)&bE2, B_ENC2);
    cudaGetSymbolAddress((void**)&bE3, B_ENC3);
    cudaGetSymbolAddress((void**)&bP1, B_P1);
    cudaGetSymbolAddress((void**)&bP2, B_P2);
    cudaGetSymbolAddress((void**)&bP3, B_P3);
    cudaGetSymbolAddress((void**)&bH0, B_H0);
    cudaGetSymbolAddress((void**)&bH1, B_H1);
    cudaGetSymbolAddress((void**)&bH2, B_H2);
    cudaGetSymbolAddress((void**)&bPE, B_PE);
    cudaGetSymbolAddress((void**)&bC,  B_C);

    float* bH[3]  = {bH0, bH1, bH2};
    float* bEN[4] = {bE0, bE1, bE2, bE3};
    float* bP[4]  = {nullptr, bP1, bP2, bP3};

    const dim3 g1(HD / 16, SEQ / TT);        // 1024-row GEMM
    const dim3 g3(3 * HD / 16, SEQ / TT);    // 3072-row gates GEMM

    // ---- level 0 precompute ----
    gemm_k<<<g1, NTHR>>>(ew1, eb1, nullptr, obs, nullptr, bG, HD, 1);
    gemm_k<<<g1, NTHR>>>(ew2, eb2, nullptr, bG, nullptr, bE0, HD, 0);
    lvl0_aux<<<SEQ, NTHR>>>(obs, qw, qb);
    gemm_k<<<g3, NTHR>>>(wih, bih, bhh, bPE, nullptr, bC, 3 * HD, 0);
    init_bar<<<1, 1>>>();
    chain_k<<<NBLK, NTHR>>>(wih, bC, bH0);

    // ---- levels 1..3 ----
    for (int l = 1; l < NLVL; l++) {
        const float* pw1l = pw1 + (size_t)l * HD * HD;
        const float* pw2l = pw2 + (size_t)l * HD * HD;
        const float* ew1l = ew1 + (size_t)l * HD * HD;
        const float* ew2l = ew2 + (size_t)l * HD * HD;
        const float* wihl = wih + (size_t)l * 4 * HD * HD;

        gemm_k<<<g1, NTHR>>>(pw1l, pb1 + l * HD, nullptr, bH[l - 1], nullptr, bG, HD, 1);
        gemm_k<<<g1, NTHR>>>(pw2l, pb2 + l * HD, nullptr, bG, nullptr, bP[l], HD, 0);
        aux_scal<<<SEQ, NTHR>>>(bEN[l - 1], bP[l], qw + l * HD, qb, l);
        gemm_k<<<g1, NTHR>>>(ew1l, eb1 + l * HD, nullptr, bEN[l - 1], bP[l], bG, HD, 1);
        gemm_k<<<g1, NTHR>>>(ew2l, eb2 + l * HD, nullptr, bG, nullptr, bEN[l], HD, 0);
        aux_pe<<<SEQ, NTHR>>>(bEN[l], l);
        if (l < 3) {
            gemm_k<<<g3, NTHR>>>(wihl, bih + (size_t)l * 4 * HD,
                                 bhh + (size_t)l * 4 * HD, bPE, nullptr, bC, 3 * HD, 0);
            init_bar<<<1, 1>>>();
            chain_k<<<NBLK, NTHR>>>(wihl, bC, bH[l]);
        }
    }
    k_epi<<<1, NTHR>>>(out);
}

// round 7
// speedup vs baseline: 5.8616x; 2.8437x over previous
#include <cuda_runtime.h>
#include <math.h>

#define NLVL 4
#define HD   1024
#define SEQ  512
#define NBLK 128
#define NTHR 256
#define NWARP 8

// ---------------- device scratch (static, no allocation) ----------------
__device__ __align__(16) float B_G   [SEQ * HD];      // gelu intermediate buffer
__device__ __align__(16) float B_ENC0[SEQ * HD];
__device__ __align__(16) float B_ENC1[SEQ * HD];
__device__ __align__(16) float B_ENC2[SEQ * HD];
__device__ __align__(16) float B_ENC3[SEQ * HD];
__device__ __align__(16) float B_P1  [SEQ * HD];
__device__ __align__(16) float B_P2  [SEQ * HD];
__device__ __align__(16) float B_P3  [SEQ * HD];
__device__ __align__(16) float B_H0  [SEQ * HD];
__device__ __align__(16) float B_H1  [SEQ * HD];
__device__ __align__(16) float B_H2  [SEQ * HD];
__device__ __align__(16) float B_PE  [SEQ * HD];      // prec * enc (per level, reused)
__device__ __align__(16) float B_C   [SEQ * 3 * HD];  // gates constant term (reused)
__device__ float B_prec[SEQ];                          // per-t prec of current level
__device__ float B_fe [4 * SEQ];                       // per-level per-t fe terms
__device__ __align__(16) float G_hbuf[2 * HD];         // double-buffered chain h
__device__ unsigned g_arrive;

// ---------------- helpers ----------------
__device__ __forceinline__ float gelu_f(float x) {
    return 0.5f * x * (1.0f + erff(x * 0.7071067811865475f));
}
__device__ __forceinline__ float sigm(float x) {
    return 1.0f / (1.0f + __expf(-x));
}

// grid-wide barrier (proven): release RMW + acquire polling on one counter
__device__ __forceinline__ void gsync(unsigned e) {
    __syncthreads();
    if (threadIdx.x == 0) {
        const unsigned target = e * NBLK;
        asm volatile("red.release.gpu.add.u32 [%0], %1;"
                     :: "l"(&g_arrive), "r"(1u) : "memory");
        unsigned v;
        do {
            asm volatile("ld.acquire.gpu.u32 %0, [%1];"
                         : "=r"(v) : "l"(&g_arrive) : "memory");
        } while (v < target);
    }
    __syncthreads();
}

// block reduce; result valid in thread 0
__device__ __forceinline__ float block_reduce(float v, float* sred) {
#pragma unroll
    for (int o = 16; o; o >>= 1) v += __shfl_xor_sync(0xffffffffu, v, o);
    int w = threadIdx.x >> 5;
    if ((threadIdx.x & 31) == 0) sred[w] = v;
    __syncthreads();
    if (threadIdx.x < 32) {
        v = (threadIdx.x < NWARP) ? sred[threadIdx.x] : 0.0f;
#pragma unroll
        for (int o = 4; o; o >>= 1) v += __shfl_xor_sync(0xffffffffu, v, o);
    }
    __syncthreads();
    return v;
}

// ---------------- init ----------------
__global__ void init_bar() { g_arrive = 0u; }

// ---------------- tiled GEMM: C[t][lr] = act(W[ar]·x_t + bias) ------------
// A = inA (-inB) : [SEQ, HD] row-major.  W: rows of K=HD contiguous.
// 64x64 tile, K-step 16, 256 threads, 4x4 per thread.
// gates mode (out_rows==3*HD): logical row lr maps to W row ar (skip forget).
__global__ void __launch_bounds__(256) gemm_k(
    const float* __restrict__ W,
    const float* __restrict__ biasA, const float* __restrict__ biasB,
    const float* __restrict__ inA,  const float* __restrict__ inB,
    float* __restrict__ outp, int out_rows, int out_gelu) {
    __shared__ __align__(16) float As[16][64];
    __shared__ __align__(16) float Bs[16][64];
    const int tid = threadIdx.x;
    const int bm = blockIdx.y * 64;            // timestep tile
    const int bn = blockIdx.x * 64;            // row tile (logical)
    const bool gates = (out_rows == 3 * HD);
    const int tm = (tid >> 4) << 2, tn = (tid & 15) << 2;
    const int lrow = tid >> 2, lk = (tid & 3) << 2;

    const int blr = bn + lrow;
    const int bar = gates ? ((blr < HD) ? blr : blr + HD) : blr;
    const float* Arow = inA + (size_t)(bm + lrow) * HD;
    const float* Brow = inB ? (inB + (size_t)(bm + lrow) * HD) : nullptr;
    const float* Wrow = W + (size_t)bar * HD;

    float acc[4][4] = {};
    for (int k0 = 0; k0 < HD; k0 += 16) {
        float4 a = *(const float4*)(Arow + k0 + lk);
        if (Brow) {
            float4 b2 = *(const float4*)(Brow + k0 + lk);
            a.x -= b2.x; a.y -= b2.y; a.z -= b2.z; a.w -= b2.w;
        }
        float4 b = *(const float4*)(Wrow + k0 + lk);
        __syncthreads();
        As[lk + 0][lrow] = a.x; As[lk + 1][lrow] = a.y;
        As[lk + 2][lrow] = a.z; As[lk + 3][lrow] = a.w;
        Bs[lk + 0][lrow] = b.x; Bs[lk + 1][lrow] = b.y;
        Bs[lk + 2][lrow] = b.z; Bs[lk + 3][lrow] = b.w;
        __syncthreads();
#pragma unroll
        for (int k = 0; k < 16; k++) {
            float4 ar4 = *(const float4*)&As[k][tm];
            float4 br4 = *(const float4*)&Bs[k][tn];
            float arr[4] = {ar4.x, ar4.y, ar4.z, ar4.w};
            float brr[4] = {br4.x, br4.y, br4.z, br4.w};
#pragma unroll
            for (int i = 0; i < 4; i++)
#pragma unroll
                for (int j = 0; j < 4; j++)
                    acc[i][j] = fmaf(arr[i], brr[j], acc[i][j]);
        }
    }
#pragma unroll
    for (int j = 0; j < 4; j++) {
        int lr = bn + tn + j;
        int ar = gates ? ((lr < HD) ? lr : lr + HD) : lr;
        float b = biasA[ar] + (biasB ? biasB[ar] : 0.0f);
#pragma unroll
        for (int i = 0; i < 4; i++) {
            float v = acc[i][j] + b;
            if (out_gelu) v = gelu_f(v);
            outp[(size_t)(bm + tm + i) * out_rows + lr] = v;
        }
    }
}

// ---------------- per-t aux kernels ----------------
__global__ void __launch_bounds__(NTHR) lvl0_aux(const float* __restrict__ obs,
                                                 const float* __restrict__ qw,
                                                 const float* __restrict__ qb) {
    __shared__ float sred[NWARP];
    __shared__ float sprec;
    const int t = blockIdx.x, tid = threadIdx.x;
    float d = 0.0f;
    for (int i = tid; i < HD; i += NTHR)
        d = fmaf(obs[(size_t)t * HD + i], qw[i], d);
    d = block_reduce(d, sred);
    if (tid == 0) sprec = sigm(d + qb[0]);
    __syncthreads();
    float prec = sprec, s = 0.0f;
    for (int i = tid; i < HD; i += NTHR) {
        float e = B_ENC0[(size_t)t * HD + i];
        B_PE[(size_t)t * HD + i] = e * prec;
        s = fmaf(e, e, s);
    }
    s = block_reduce(s, sred);
    if (tid == 0) B_fe[t] = s * prec;
}

__global__ void __launch_bounds__(NTHR) aux_scal(const float* __restrict__ encprev,
                                                 const float* __restrict__ P,
                                                 const float* __restrict__ qwl,
                                                 const float* __restrict__ qb, int l) {
    __shared__ float sred[NWARP];
    const int t = blockIdx.x, tid = threadIdx.x;
    float d = 0.0f;
    for (int i = tid; i < HD; i += NTHR) {
        float e = encprev[(size_t)t * HD + i] - P[(size_t)t * HD + i];
        d = fmaf(e, qwl[i], d);
    }
    d = block_reduce(d, sred);
    if (tid == 0) B_prec[t] = sigm(d + qb[l]);
}

__global__ void __launch_bounds__(NTHR) aux_pe(const float* __restrict__ enc, int l) {
    __shared__ float sred[NWARP];
    const int t = blockIdx.x, tid = threadIdx.x;
    float prec = B_prec[t], s = 0.0f;
    for (int i = tid; i < HD; i += NTHR) {
        float e = enc[(size_t)t * HD + i];
        B_PE[(size_t)t * HD + i] = e * prec;
        s = fmaf(e, e, s);
    }
    s = block_reduce(s, sred);
    if (tid == 0) B_fe[l * SEQ + t] = s * prec;
}

// ---------------- sequential LSTM chain: register-resident weights --------
// warp gw owns logical rows {gw, gw+HD, gw+2HD} -> W rows {gw, gw+2HD, gw+3HD}.
// lane 0 of warp gw ends up holding all 3 gate pre-acts of element gw, so it
// computes h(gw) locally BEFORE the barrier and publishes ONE float.
__global__ void __launch_bounds__(NTHR, 1) chain_k(const float* __restrict__ Wih,
                                                   const float* __restrict__ C,
                                                   float* __restrict__ Hout) {
    __shared__ __align__(16) float sx[HD];
    const int tid = threadIdx.x, lane = tid & 31, wid = tid >> 5;
    const int gw = blockIdx.x * NWARP + wid;   // 0..1023
    unsigned epoch = 0;

    // preload 3 weight rows into registers (one-time 12 MB grid-wide read)
    float4 wr0[8], wr1[8], wr2[8];
    {
        const float4* w0 = (const float4*)(Wih + (size_t)gw * HD);
        const float4* w1 = (const float4*)(Wih + (size_t)(gw + 2 * HD) * HD);
        const float4* w2 = (const float4*)(Wih + (size_t)(gw + 3 * HD) * HD);
#pragma unroll
        for (int k = 0; k < 8; k++) {
            wr0[k] = w0[lane + 32 * k];
            wr1[k] = w1[lane + 32 * k];
            wr2[k] = w2[lane + 32 * k];
        }
    }

    for (int t = 0; t < SEQ; t++) {
        float r0 = 0.0f, r1 = 0.0f, r2 = 0.0f;
        if (t > 0) {
            // broadcast-load h(t-1) from L2 into smem
            const float* hsrc = &G_hbuf[((t - 1) & 1) * HD];
            for (int i = tid * 4; i < HD; i += NTHR * 4) {
                float4 hv4 = __ldcg((const float4*)(hsrc + i));
                *(float4*)&sx[i] = hv4;
            }
            __syncthreads();
            const float4* p = (const float4*)sx;
#pragma unroll
            for (int k = 0; k < 8; k++) {
                float4 x = p[lane + 32 * k];
                r0 = fmaf(wr0[k].x, x.x, r0); r0 = fmaf(wr0[k].y, x.y, r0);
                r0 = fmaf(wr0[k].z, x.z, r0); r0 = fmaf(wr0[k].w, x.w, r0);
                r1 = fmaf(wr1[k].x, x.x, r1); r1 = fmaf(wr1[k].y, x.y, r1);
                r1 = fmaf(wr1[k].z, x.z, r1); r1 = fmaf(wr1[k].w, x.w, r1);
                r2 = fmaf(wr2[k].x, x.x, r2); r2 = fmaf(wr2[k].y, x.y, r2);
                r2 = fmaf(wr2[k].z, x.z, r2); r2 = fmaf(wr2[k].w, x.w, r2);
            }
#pragma unroll
            for (int o = 16; o; o >>= 1) {
                r0 += __shfl_xor_sync(0xffffffffu, r0, o);
                r1 += __shfl_xor_sync(0xffffffffu, r1, o);
                r2 += __shfl_xor_sync(0xffffffffu, r2, o);
            }
            __syncthreads();   // sx reads done before next overwrite
        }
        if (lane == 0) {
            const float* Ct = C + (size_t)t * 3 * HD;
            float zi = r0 + Ct[gw];
            float zg = r1 + Ct[gw + HD];
            float zo = r2 + Ct[gw + 2 * HD];
            float hv = sigm(zo) * tanhf(sigm(zi) * tanhf(zg));
            Hout[(size_t)t * HD + gw] = hv;
            __stcg(&G_hbuf[(t & 1) * HD + gw], hv);
        }
        gsync(++epoch);
    }
}

// ---------------- epilogue ----------------
__global__ void __launch_bounds__(NTHR) k_epi(float* __restrict__ out) {
    __shared__ float sred[NWARP];
    const int tid = threadIdx.x;
    const size_t last = (size_t)(SEQ - 1) * HD;
    for (int i = tid; i < HD; i += NTHR) {
        out[i] = 0.0f;                              // pred level 0 == 0
        out[1 * HD + i] = B_P1[last + i];
        out[2 * HD + i] = B_P2[last + i];
        out[3 * HD + i] = B_P3[last + i];
        out[4 * HD + i] = B_ENC0[last + i];         // err level 0 = enc0
        out[5 * HD + i] = B_ENC1[last + i];
        out[6 * HD + i] = B_ENC2[last + i];
        out[7 * HD + i] = B_ENC3[last + i];
    }
    float s = 0.0f;
    for (int t = tid; t < SEQ; t += NTHR)
        s += B_fe[t] + B_fe[SEQ + t] + B_fe[2 * SEQ + t] + B_fe[3 * SEQ + t];
    s = block_reduce(s, sred);
    if (tid == 0) out[8 * HD] = s;
}

// ---------------- launch ----------------
extern "C" void kernel_launch(void* const* d_in, const int* in_sizes, int n_in,
                              void* d_out, int out_size) {
    (void)n_in; (void)out_size;
    const float *obs, *pw1, *pb1, *pw2, *pb2, *ew1, *eb1, *ew2, *eb2;
    const float *qw, *qb, *wih, *bih, *bhh;
    if (in_sizes[0] == SEQ * HD) {
        obs = (const float*)d_in[0];
        pw1 = (const float*)d_in[1];  pb1 = (const float*)d_in[2];
        pw2 = (const float*)d_in[3];  pb2 = (const float*)d_in[4];
        ew1 = (const float*)d_in[5];  eb1 = (const float*)d_in[6];
        ew2 = (const float*)d_in[7];  eb2 = (const float*)d_in[8];
        qw  = (const float*)d_in[9];  qb  = (const float*)d_in[10];
        wih = (const float*)d_in[11];  // whh unused
        bih = (const float*)d_in[13]; bhh = (const float*)d_in[14];
    } else {
        bhh = (const float*)d_in[0];  bih = (const float*)d_in[1];
        eb1 = (const float*)d_in[2];  eb2 = (const float*)d_in[3];
        ew1 = (const float*)d_in[4];  ew2 = (const float*)d_in[5];
        obs = (const float*)d_in[6];
        pb1 = (const float*)d_in[7];  pb2 = (const float*)d_in[8];
        pw1 = (const float*)d_in[9];  pw2 = (const float*)d_in[10];
        qb  = (const float*)d_in[11]; qw  = (const float*)d_in[12];
        wih = (const float*)d_in[14];  // whh unused
    }
    float* out = (float*)d_out;

    float *bG, *bE0, *bE1, *bE2, *bE3, *bP1, *bP2, *bP3, *bH0, *bH1, *bH2, *bPE, *bC;
    cudaGetSymbolAddress((void**)&bG,  B_G);
    cudaGetSymbolAddress((void**)&bE0, B_ENC0);
    cudaGetSymbolAddress((void**)&bE1, B_ENC1);
    cudaGetSymbolAddress((void**)&bE2, B_ENC2);
    cudaGetSymbolAddress((void**)&bE3, B_ENC3);
    cudaGetSymbolAddress((void**)&bP1, B_P1);
    cudaGetSymbolAddress((void**)&bP2, B_P2);
    cudaGetSymbolAddress((void**)&bP3, B_P3);
    cudaGetSymbolAddress((void**)&bH0, B_H0);
    cudaGetSymbolAddress((void**)&bH1, B_H1);
    cudaGetSymbolAddress((void**)&bH2, B_H2);
    cudaGetSymbolAddress((void**)&bPE, B_PE);
    cudaGetSymbolAddress((void**)&bC,  B_C);

    float* bH[3]  = {bH0, bH1, bH2};
    float* bEN[4] = {bE0, bE1, bE2, bE3};
    float* bP[4]  = {nullptr, bP1, bP2, bP3};

    const dim3 g1(HD / 64, SEQ / 64);        // (16, 8)  = 128 blocks
    const dim3 g3(3 * HD / 64, SEQ / 64);    // (48, 8)  = 384 blocks

    // ---- level 0 precompute ----
    gemm_k<<<g1, 256>>>(ew1, eb1, nullptr, obs, nullptr, bG, HD, 1);
    gemm_k<<<g1, 256>>>(ew2, eb2, nullptr, bG, nullptr, bE0, HD, 0);
    lvl0_aux<<<SEQ, NTHR>>>(obs, qw, qb);
    gemm_k<<<g3, 256>>>(wih, bih, bhh, bPE, nullptr, bC, 3 * HD, 0);
    init_bar<<<1, 1>>>();
    chain_k<<<NBLK, NTHR>>>(wih, bC, bH0);

    // ---- levels 1..3 ----
    for (int l = 1; l < NLVL; l++) {
        const float* pw1l = pw1 + (size_t)l * HD * HD;
        const float* pw2l = pw2 + (size_t)l * HD * HD;
        const float* ew1l = ew1 + (size_t)l * HD * HD;
        const float* ew2l = ew2 + (size_t)l * HD * HD;
        const float* wihl = wih + (size_t)l * 4 * HD * HD;

        gemm_k<<<g1, 256>>>(pw1l, pb1 + l * HD, nullptr, bH[l - 1], nullptr, bG, HD, 1);
        gemm_k<<<g1, 256>>>(pw2l, pb2 + l * HD, nullptr, bG, nullptr, bP[l], HD, 0);
        aux_scal<<<SEQ, NTHR>>>(bEN[l - 1], bP[l], qw + l * HD, qb, l);
        gemm_k<<<g1, 256>>>(ew1l, eb1 + l * HD, nullptr, bEN[l - 1], bP[l], bG, HD, 1);
        gemm_k<<<g1, 256>>>(ew2l, eb2 + l * HD, nullptr, bG, nullptr, bEN[l], HD, 0);
        aux_pe<<<SEQ, NTHR>>>(bEN[l], l);
        if (l < 3) {
            gemm_k<<<g3, 256>>>(wihl, bih + (size_t)l * 4 * HD,
                                bhh + (size_t)l * 4 * HD, bPE, nullptr, bC, 3 * HD, 0);
            init_bar<<<1, 1>>>();
            chain_k<<<NBLK, NTHR>>>(wihl, bC, bH[l]);
        }
    }
    k_epi<<<1, NTHR>>>(out);
}

// round 9
// speedup vs baseline: 5.9802x; 1.0202x over previous
#include <cuda_runtime.h>
#include <math.h>

#define NLVL 4
#define HD   1024
#define SEQ  512
#define NBLK 128
#define NTHR 256
#define NWARP 8
#define FLAGF 2.0f            // impossible h value: |h| < 1 always
#define PADW 68               // smem row pad: 2-way max bank conflict

// ---------------- device scratch (static, no allocation) ----------------
__device__ __align__(16) float B_G   [SEQ * HD];      // gelu intermediate buffer
__device__ __align__(16) float B_ENC0[SEQ * HD];
__device__ __align__(16) float B_ENC1[SEQ * HD];
__device__ __align__(16) float B_ENC2[SEQ * HD];
__device__ __align__(16) float B_ENC3[SEQ * HD];
__device__ __align__(16) float B_P1  [SEQ * HD];
__device__ __align__(16) float B_P2  [SEQ * HD];
__device__ __align__(16) float B_P3  [SEQ * HD];
__device__ __align__(16) float B_H0  [SEQ * HD];
__device__ __align__(16) float B_H1  [SEQ * HD];
__device__ __align__(16) float B_H2  [SEQ * HD];
__device__ __align__(16) float B_PE  [SEQ * HD];      // prec * enc (per level, reused)
__device__ __align__(16) float B_C   [SEQ * 3 * HD];  // gates constant term (reused)
__device__ float B_prec[SEQ];                          // per-t prec of current level
__device__ float B_fe [4 * SEQ];                       // per-level per-t fe terms

// ---------------- helpers ----------------
__device__ __forceinline__ float gelu_f(float x) {
    return 0.5f * x * (1.0f + erff(x * 0.7071067811865475f));
}
__device__ __forceinline__ float sigm(float x) {
    return 1.0f / (1.0f + __expf(-x));
}

// morally-strong (coherent) scalar ops — the PTX memory model guarantees
// per-location coherence ONLY for .relaxed/.acquire/.release scoped ops.
// (.cg/.plain are WEAK: a weak poll may legally read stale data — the R8 bug.)
__device__ __forceinline__ float ld_relaxed(const float* p) {
    float v;
    asm volatile("ld.relaxed.gpu.global.f32 %0, [%1];" : "=f"(v) : "l"(p) : "memory");
    return v;
}
__device__ __forceinline__ void st_release(float* p, float v) {
    asm volatile("st.release.gpu.global.f32 [%0], %1;" :: "l"(p), "f"(v) : "memory");
}

// block reduce; result valid in thread 0
__device__ __forceinline__ float block_reduce(float v, float* sred) {
#pragma unroll
    for (int o = 16; o; o >>= 1) v += __shfl_xor_sync(0xffffffffu, v, o);
    int w = threadIdx.x >> 5;
    if ((threadIdx.x & 31) == 0) sred[w] = v;
    __syncthreads();
    if (threadIdx.x < 32) {
        v = (threadIdx.x < NWARP) ? sred[threadIdx.x] : 0.0f;
#pragma unroll
        for (int o = 4; o; o >>= 1) v += __shfl_xor_sync(0xffffffffu, v, o);
    }
    __syncthreads();
    return v;
}

// ---------------- flag prefill (runs every replay, before chains) --------
__global__ void flag_fill() {
    size_t i = (size_t)blockIdx.x * blockDim.x + threadIdx.x;
    if (i < (size_t)SEQ * HD) {
        B_H0[i] = FLAGF; B_H1[i] = FLAGF; B_H2[i] = FLAGF;
    }
}

// ---------------- tiled GEMM (round-7 proven + smem padding) -------------
__global__ void __launch_bounds__(256) gemm_k(
    const float* __restrict__ W,
    const float* __restrict__ biasA, const float* __restrict__ biasB,
    const float* __restrict__ inA,  const float* __restrict__ inB,
    float* __restrict__ outp, int out_rows, int out_gelu) {
    __shared__ __align__(16) float As[16][PADW];
    __shared__ __align__(16) float Bs[16][PADW];
    const int tid = threadIdx.x;
    const int bm = blockIdx.y * 64;            // timestep tile
    const int bn = blockIdx.x * 64;            // row tile (logical)
    const bool gates = (out_rows == 3 * HD);
    const int tm = (tid >> 4) << 2, tn = (tid & 15) << 2;
    const int lrow = tid >> 2, lk = (tid & 3) << 2;

    const int blr = bn + lrow;
    const int bar = gates ? ((blr < HD) ? blr : blr + HD) : blr;
    const float* Arow = inA + (size_t)(bm + lrow) * HD;
    const float* Brow = inB ? (inB + (size_t)(bm + lrow) * HD) : nullptr;
    const float* Wrow = W + (size_t)bar * HD;

    float acc[4][4] = {};
    for (int k0 = 0; k0 < HD; k0 += 16) {
        float4 a = *(const float4*)(Arow + k0 + lk);
        if (Brow) {
            float4 b2 = *(const float4*)(Brow + k0 + lk);
            a.x -= b2.x; a.y -= b2.y; a.z -= b2.z; a.w -= b2.w;
        }
        float4 b = *(const float4*)(Wrow + k0 + lk);
        __syncthreads();
        As[lk + 0][lrow] = a.x; As[lk + 1][lrow] = a.y;
        As[lk + 2][lrow] = a.z; As[lk + 3][lrow] = a.w;
        Bs[lk + 0][lrow] = b.x; Bs[lk + 1][lrow] = b.y;
        Bs[lk + 2][lrow] = b.z; Bs[lk + 3][lrow] = b.w;
        __syncthreads();
#pragma unroll
        for (int k = 0; k < 16; k++) {
            float4 ar4 = *(const float4*)&As[k][tm];
            float4 br4 = *(const float4*)&Bs[k][tn];
            float arr[4] = {ar4.x, ar4.y, ar4.z, ar4.w};
            float brr[4] = {br4.x, br4.y, br4.z, br4.w};
#pragma unroll
            for (int i = 0; i < 4; i++)
#pragma unroll
                for (int j = 0; j < 4; j++)
                    acc[i][j] = fmaf(arr[i], brr[j], acc[i][j]);
        }
    }
#pragma unroll
    for (int j = 0; j < 4; j++) {
        int lr = bn + tn + j;
        int ar = gates ? ((lr < HD) ? lr : lr + HD) : lr;
        float b = biasA[ar] + (biasB ? biasB[ar] : 0.0f);
#pragma unroll
        for (int i = 0; i < 4; i++) {
            float v = acc[i][j] + b;
            if (out_gelu) v = gelu_f(v);
            outp[(size_t)(bm + tm + i) * out_rows + lr] = v;
        }
    }
}

// ---------------- per-t aux kernels ----------------
__global__ void __launch_bounds__(NTHR) lvl0_aux(const float* __restrict__ obs,
                                                 const float* __restrict__ qw,
                                                 const float* __restrict__ qb) {
    __shared__ float sred[NWARP];
    __shared__ float sprec;
    const int t = blockIdx.x, tid = threadIdx.x;
    float d = 0.0f;
    for (int i = tid; i < HD; i += NTHR)
        d = fmaf(obs[(size_t)t * HD + i], qw[i], d);
    d = block_reduce(d, sred);
    if (tid == 0) sprec = sigm(d + qb[0]);
    __syncthreads();
    float prec = sprec, s = 0.0f;
    for (int i = tid; i < HD; i += NTHR) {
        float e = B_ENC0[(size_t)t * HD + i];
        B_PE[(size_t)t * HD + i] = e * prec;
        s = fmaf(e, e, s);
    }
    s = block_reduce(s, sred);
    if (tid == 0) B_fe[t] = s * prec;
}

__global__ void __launch_bounds__(NTHR) aux_scal(const float* __restrict__ encprev,
                                                 const float* __restrict__ P,
                                                 const float* __restrict__ qwl,
                                                 const float* __restrict__ qb, int l) {
    __shared__ float sred[NWARP];
    const int t = blockIdx.x, tid = threadIdx.x;
    float d = 0.0f;
    for (int i = tid; i < HD; i += NTHR) {
        float e = encprev[(size_t)t * HD + i] - P[(size_t)t * HD + i];
        d = fmaf(e, qwl[i], d);
    }
    d = block_reduce(d, sred);
    if (tid == 0) B_prec[t] = sigm(d + qb[l]);
}

__global__ void __launch_bounds__(NTHR) aux_pe(const float* __restrict__ enc, int l) {
    __shared__ float sred[NWARP];
    const int t = blockIdx.x, tid = threadIdx.x;
    float prec = B_prec[t], s = 0.0f;
    for (int i = tid; i < HD; i += NTHR) {
        float e = enc[(size_t)t * HD + i];
        B_PE[(size_t)t * HD + i] = e * prec;
        s = fmaf(e, e, s);
    }
    s = block_reduce(s, sred);
    if (tid == 0) B_fe[l * SEQ + t] = s * prec;
}

// ---------------- sequential LSTM chain: coherent data-flow sync ----------
// warp gw owns W rows {gw, gw+2HD, gw+3HD} in registers. lane 0 holds all 3
// gate pre-acts of element gw -> computes h(gw), publishes ONE float with a
// RELEASE store. Consumers poll Hout[t-1] with RELAXED (coherent) loads.
__global__ void __launch_bounds__(NTHR, 1) chain_k(const float* __restrict__ Wih,
                                                   const float* __restrict__ C,
                                                   float* __restrict__ Hout) {
    __shared__ __align__(16) float sx[HD];
    const int tid = threadIdx.x, lane = tid & 31, wid = tid >> 5;
    const int gw = blockIdx.x * NWARP + wid;   // 0..1023

    // preload 3 weight rows into registers (one-time read)
    float4 wr0[8], wr1[8], wr2[8];
    {
        const float4* w0 = (const float4*)(Wih + (size_t)gw * HD);
        const float4* w1 = (const float4*)(Wih + (size_t)(gw + 2 * HD) * HD);
        const float4* w2 = (const float4*)(Wih + (size_t)(gw + 3 * HD) * HD);
#pragma unroll
        for (int k = 0; k < 8; k++) {
            wr0[k] = w0[lane + 32 * k];
            wr1[k] = w1[lane + 32 * k];
            wr2[k] = w2[lane + 32 * k];
        }
    }

    for (int t = 0; t < SEQ; t++) {
        // prefetch C(t) off the critical path (independent of h)
        float c0 = 0.0f, c1 = 0.0f, c2 = 0.0f;
        if (lane == 0) {
            const float* Ct = C + (size_t)t * 3 * HD;
            c0 = Ct[gw]; c1 = Ct[gw + HD]; c2 = Ct[gw + 2 * HD];
        }

        float r0 = 0.0f, r1 = 0.0f, r2 = 0.0f;
        if (t > 0) {
            // poll-load h(t-1): 4 coherent relaxed loads per thread (MLP=4)
            const float* src = Hout + (size_t)(t - 1) * HD + tid * 4;
            float v0, v1, v2, v3;
            do {
                v0 = ld_relaxed(src + 0);
                v1 = ld_relaxed(src + 1);
                v2 = ld_relaxed(src + 2);
                v3 = ld_relaxed(src + 3);
            } while (v0 == FLAGF || v1 == FLAGF || v2 == FLAGF || v3 == FLAGF);
            sx[tid * 4 + 0] = v0; sx[tid * 4 + 1] = v1;
            sx[tid * 4 + 2] = v2; sx[tid * 4 + 3] = v3;
            __syncthreads();

            const float4* p = (const float4*)sx;
#pragma unroll
            for (int k = 0; k < 8; k++) {
                float4 x = p[lane + 32 * k];
                r0 = fmaf(wr0[k].x, x.x, r0); r0 = fmaf(wr0[k].y, x.y, r0);
                r0 = fmaf(wr0[k].z, x.z, r0); r0 = fmaf(wr0[k].w, x.w, r0);
                r1 = fmaf(wr1[k].x, x.x, r1); r1 = fmaf(wr1[k].y, x.y, r1);
                r1 = fmaf(wr1[k].z, x.z, r1); r1 = fmaf(wr1[k].w, x.w, r1);
                r2 = fmaf(wr2[k].x, x.x, r2); r2 = fmaf(wr2[k].y, x.y, r2);
                r2 = fmaf(wr2[k].z, x.z, r2); r2 = fmaf(wr2[k].w, x.w, r2);
            }
#pragma unroll
            for (int o = 16; o; o >>= 1) {
                r0 += __shfl_xor_sync(0xffffffffu, r0, o);
                r1 += __shfl_xor_sync(0xffffffffu, r1, o);
                r2 += __shfl_xor_sync(0xffffffffu, r2, o);
            }
        }
        if (lane == 0) {
            float zi = r0 + c0;
            float zg = r1 + c1;
            float zo = r2 + c2;
            float hv = sigm(zo) * tanhf(sigm(zi) * tanhf(zg));
            st_release(&Hout[(size_t)t * HD + gw], hv);   // coherent publish
        }
        __syncthreads();    // protect sx before next iteration's overwrite
    }
}

// ---------------- epilogue ----------------
__global__ void __launch_bounds__(NTHR) k_epi(float* __restrict__ out) {
    __shared__ float sred[NWARP];
    const int tid = threadIdx.x;
    const size_t last = (size_t)(SEQ - 1) * HD;
    for (int i = tid; i < HD; i += NTHR) {
        out[i] = 0.0f;                              // pred level 0 == 0
        out[1 * HD + i] = B_P1[last + i];
        out[2 * HD + i] = B_P2[last + i];
        out[3 * HD + i] = B_P3[last + i];
        out[4 * HD + i] = B_ENC0[last + i];         // err level 0 = enc0
        out[5 * HD + i] = B_ENC1[last + i];
        out[6 * HD + i] = B_ENC2[last + i];
        out[7 * HD + i] = B_ENC3[last + i];
    }
    float s = 0.0f;
    for (int t = tid; t < SEQ; t += NTHR)
        s += B_fe[t] + B_fe[SEQ + t] + B_fe[2 * SEQ + t] + B_fe[3 * SEQ + t];
    s = block_reduce(s, sred);
    if (tid == 0) out[8 * HD] = s;
}

// ---------------- launch ----------------
extern "C" void kernel_launch(void* const* d_in, const int* in_sizes, int n_in,
                              void* d_out, int out_size) {
    (void)n_in; (void)out_size;
    const float *obs, *pw1, *pb1, *pw2, *pb2, *ew1, *eb1, *ew2, *eb2;
    const float *qw, *qb, *wih, *bih, *bhh;
    if (in_sizes[0] == SEQ * HD) {
        obs = (const float*)d_in[0];
        pw1 = (const float*)d_in[1];  pb1 = (const float*)d_in[2];
        pw2 = (const float*)d_in[3];  pb2 = (const float*)d_in[4];
        ew1 = (const float*)d_in[5];  eb1 = (const float*)d_in[6];
        ew2 = (const float*)d_in[7];  eb2 = (const float*)d_in[8];
        qw  = (const float*)d_in[9];  qb  = (const float*)d_in[10];
        wih = (const float*)d_in[11];  // whh unused
        bih = (const float*)d_in[13]; bhh = (const float*)d_in[14];
    } else {
        bhh = (const float*)d_in[0];  bih = (const float*)d_in[1];
        eb1 = (const float*)d_in[2];  eb2 = (const float*)d_in[3];
        ew1 = (const float*)d_in[4];  ew2 = (const float*)d_in[5];
        obs = (const float*)d_in[6];
        pb1 = (const float*)d_in[7];  pb2 = (const float*)d_in[8];
        pw1 = (const float*)d_in[9];  pw2 = (const float*)d_in[10];
        qb  = (const float*)d_in[11]; qw  = (const float*)d_in[12];
        wih = (const float*)d_in[14];  // whh unused
    }
    float* out = (float*)d_out;

    float *bG, *bE0, *bE1, *bE2, *bE3, *bP1, *bP2, *bP3, *bH0, *bH1, *bH2, *bPE, *bC;
    cudaGetSymbolAddress((void**)&bG,  B_G);
    cudaGetSymbolAddress((void**)&bE0, B_ENC0);
    cudaGetSymbolAddress((void**)&bE1, B_ENC1);
    cudaGetSymbolAddress((void**)&bE2, B_ENC2);
    cudaGetSymbolAddress((void**)&bE3, B_ENC3);
    cudaGetSymbolAddress((void**)&bP1, B_P1);
    cudaGetSymbolAddress((void**)&bP2, B_P2);
    cudaGetSymbolAddress((void**)&bP3, B_P3);
    cudaGetSymbolAddress((void**)&bH0, B_H0);
    cudaGetSymbolAddress((void**)&bH1, B_H1);
    cudaGetSymbolAddress((void**)&bH2, B_H2);
    cudaGetSymbolAddress((void**)&bPE, B_PE);
    cudaGetSymbolAddress((void**)&bC,  B_C);

    float* bH[3]  = {bH0, bH1, bH2};
    float* bEN[4] = {bE0, bE1, bE2, bE3};
    float* bP[4]  = {nullptr, bP1, bP2, bP3};

    const dim3 g1(HD / 64, SEQ / 64);        // (16, 8)  = 128 blocks
    const dim3 g3(3 * HD / 64, SEQ / 64);    // (48, 8)  = 384 blocks

    // reset h buffers to FLAG (must run every replay, before any chain)
    flag_fill<<<(SEQ * HD + NTHR - 1) / NTHR, NTHR>>>();

    // ---- level 0 precompute ----
    gemm_k<<<g1, 256>>>(ew1, eb1, nullptr, obs, nullptr, bG, HD, 1);
    gemm_k<<<g1, 256>>>(ew2, eb2, nullptr, bG, nullptr, bE0, HD, 0);
    lvl0_aux<<<SEQ, NTHR>>>(obs, qw, qb);
    gemm_k<<<g3, 256>>>(wih, bih, bhh, bPE, nullptr, bC, 3 * HD, 0);
    chain_k<<<NBLK, NTHR>>>(wih, bC, bH0);

    // ---- levels 1..3 ----
    for (int l = 1; l < NLVL; l++) {
        const float* pw1l = pw1 + (size_t)l * HD * HD;
        const float* pw2l = pw2 + (size_t)l * HD * HD;
        const float* ew1l = ew1 + (size_t)l * HD * HD;
        const float* ew2l = ew2 + (size_t)l * HD * HD;
        const float* wihl = wih + (size_t)l * 4 * HD * HD;

        gemm_k<<<g1, 256>>>(pw1l, pb1 + l * HD, nullptr, bH[l - 1], nullptr, bG, HD, 1);
        gemm_k<<<g1, 256>>>(pw2l, pb2 + l * HD, nullptr, bG, nullptr, bP[l], HD, 0);
        aux_scal<<<SEQ, NTHR>>>(bEN[l - 1], bP[l], qw + l * HD, qb, l);
        gemm_k<<<g1, 256>>>(ew1l, eb1 + l * HD, nullptr, bEN[l - 1], bP[l], bG, HD, 1);
        gemm_k<<<g1, 256>>>(ew2l, eb2 + l * HD, nullptr, bG, nullptr, bEN[l], HD, 0);
        aux_pe<<<SEQ, NTHR>>>(bEN[l], l);
        if (l < 3) {
            gemm_k<<<g3, 256>>>(wihl, bih + (size_t)l * 4 * HD,
                                bhh + (size_t)l * 4 * HD, bPE, nullptr, bC, 3 * HD, 0);
            chain_k<<<NBLK, NTHR>>>(wihl, bC, bH[l]);
        }
    }
    k_epi<<<1, NTHR>>>(out);
}

// round 10
// speedup vs baseline: 6.3624x; 1.0639x over previous
#include <cuda_runtime.h>
#include <math.h>

#define NLVL 4
#define HD   1024
#define SEQ  512
#define NBLK 128
#define NTHR 256
#define NWARP 8
#define FLAGF 2.0f            // impossible h value: |h| < 1 always

// ---------------- device scratch (static, no allocation) ----------------
__device__ __align__(16) float B_G   [SEQ * HD];      // gelu intermediate buffer
__device__ __align__(16) float B_ENC0[SEQ * HD];
__device__ __align__(16) float B_ENC1[SEQ * HD];
__device__ __align__(16) float B_ENC2[SEQ * HD];
__device__ __align__(16) float B_ENC3[SEQ * HD];
__device__ __align__(16) float B_P1  [SEQ * HD];
__device__ __align__(16) float B_P2  [SEQ * HD];
__device__ __align__(16) float B_P3  [SEQ * HD];
__device__ __align__(16) float B_H0  [SEQ * HD];
__device__ __align__(16) float B_H1  [SEQ * HD];
__device__ __align__(16) float B_H2  [SEQ * HD];
__device__ __align__(16) float B_PE  [SEQ * HD];      // prec * enc (per level, reused)
__device__ float B_prec[SEQ];                          // per-t prec of current level
__device__ float B_fe [4 * SEQ];                       // per-level per-t fe terms

// ---------------- helpers ----------------
__device__ __forceinline__ float gelu_f(float x) {
    return 0.5f * x * (1.0f + erff(x * 0.7071067811865475f));
}
__device__ __forceinline__ float sigm(float x) {
    return 1.0f / (1.0f + __expf(-x));
}

// morally-strong (coherent) scalar ops — per-location coherence is guaranteed
// ONLY for .relaxed/.acquire/.release scoped ops (weak .cg polls read stale).
__device__ __forceinline__ float ld_relaxed(const float* p) {
    float v;
    asm volatile("ld.relaxed.gpu.global.f32 %0, [%1];" : "=f"(v) : "l"(p) : "memory");
    return v;
}
__device__ __forceinline__ void st_release(float* p, float v) {
    asm volatile("st.release.gpu.global.f32 [%0], %1;" :: "l"(p), "f"(v) : "memory");
}

// block reduce; result valid in thread 0
__device__ __forceinline__ float block_reduce(float v, float* sred) {
#pragma unroll
    for (int o = 16; o; o >>= 1) v += __shfl_xor_sync(0xffffffffu, v, o);
    int w = threadIdx.x >> 5;
    if ((threadIdx.x & 31) == 0) sred[w] = v;
    __syncthreads();
    if (threadIdx.x < 32) {
        v = (threadIdx.x < NWARP) ? sred[threadIdx.x] : 0.0f;
#pragma unroll
        for (int o = 4; o; o >>= 1) v += __shfl_xor_sync(0xffffffffu, v, o);
    }
    __syncthreads();
    return v;
}

// ---------------- flag prefill (runs every replay, before chains) --------
__global__ void flag_fill() {
    size_t i = (size_t)blockIdx.x * blockDim.x + threadIdx.x;
    if (i < (size_t)SEQ * HD) {
        B_H0[i] = FLAGF; B_H1[i] = FLAGF; B_H2[i] = FLAGF;
    }
}

// ---------------- tiled GEMM: 64 timesteps x 32 rows per block -----------
// out[t][r] = act( W[r]·x_t + bias[r] ),  x_t = inA[t] (- inB[t] if inB)
// grid (HD/32, SEQ/64) = 256 blocks -> ~2 blocks/SM -> 4 warps/SMSP issue.
__global__ void __launch_bounds__(256) gemm_k(
    const float* __restrict__ W,    const float* __restrict__ bias,
    const float* __restrict__ inA,  const float* __restrict__ inB,
    float* __restrict__ outp, int out_gelu) {
    __shared__ __align__(16) float As[16][68];   // [k][t]
    __shared__ __align__(16) float Bs[16][34];   // [k][r]
    const int tid = threadIdx.x;
    const int bm = blockIdx.y * 64;              // timestep tile
    const int bn = blockIdx.x * 32;              // row tile
    const int tm = (tid >> 4) << 2;              // 0..60 (4 t per thread)
    const int tn = (tid & 15) << 1;              // 0..30 (2 rows per thread)
    const int lrow = tid >> 2, lk = (tid & 3) << 2;

    const float* Arow = inA + (size_t)(bm + lrow) * HD;
    const float* Brow = inB ? (inB + (size_t)(bm + lrow) * HD) : nullptr;
    const float* Wrow = W + (size_t)(bn + (tid >> 2)) * HD;  // valid for tid<128

    float acc[4][2] = {};
    for (int k0 = 0; k0 < HD; k0 += 16) {
        float4 a = *(const float4*)(Arow + k0 + lk);
        if (Brow) {
            float4 b2 = *(const float4*)(Brow + k0 + lk);
            a.x -= b2.x; a.y -= b2.y; a.z -= b2.z; a.w -= b2.w;
        }
        float4 w4 = make_float4(0.f, 0.f, 0.f, 0.f);
        if (tid < 128) w4 = *(const float4*)(Wrow + k0 + lk);
        __syncthreads();
        As[lk + 0][lrow] = a.x; As[lk + 1][lrow] = a.y;
        As[lk + 2][lrow] = a.z; As[lk + 3][lrow] = a.w;
        if (tid < 128) {
            Bs[lk + 0][lrow] = w4.x; Bs[lk + 1][lrow] = w4.y;
            Bs[lk + 2][lrow] = w4.z; Bs[lk + 3][lrow] = w4.w;
        }
        __syncthreads();
#pragma unroll
        for (int k = 0; k < 16; k++) {
            float4 a4 = *(const float4*)&As[k][tm];
            float2 b2 = *(const float2*)&Bs[k][tn];
            acc[0][0] = fmaf(a4.x, b2.x, acc[0][0]);
            acc[0][1] = fmaf(a4.x, b2.y, acc[0][1]);
            acc[1][0] = fmaf(a4.y, b2.x, acc[1][0]);
            acc[1][1] = fmaf(a4.y, b2.y, acc[1][1]);
            acc[2][0] = fmaf(a4.z, b2.x, acc[2][0]);
            acc[2][1] = fmaf(a4.z, b2.y, acc[2][1]);
            acc[3][0] = fmaf(a4.w, b2.x, acc[3][0]);
            acc[3][1] = fmaf(a4.w, b2.y, acc[3][1]);
        }
    }
    const float b0 = bias[bn + tn], b1 = bias[bn + tn + 1];
#pragma unroll
    for (int i = 0; i < 4; i++) {
        float v0 = acc[i][0] + b0;
        float v1 = acc[i][1] + b1;
        if (out_gelu) { v0 = gelu_f(v0); v1 = gelu_f(v1); }
        *(float2*)&outp[(size_t)(bm + tm + i) * HD + bn + tn] = make_float2(v0, v1);
    }
}

// ---------------- per-t aux kernels ----------------
__global__ void __launch_bounds__(NTHR) lvl0_aux(const float* __restrict__ obs,
                                                 const float* __restrict__ qw,
                                                 const float* __restrict__ qb) {
    __shared__ float sred[NWARP];
    __shared__ float sprec;
    const int t = blockIdx.x, tid = threadIdx.x;
    float d = 0.0f;
    for (int i = tid; i < HD; i += NTHR)
        d = fmaf(obs[(size_t)t * HD + i], qw[i], d);
    d = block_reduce(d, sred);
    if (tid == 0) sprec = sigm(d + qb[0]);
    __syncthreads();
    float prec = sprec, s = 0.0f;
    for (int i = tid; i < HD; i += NTHR) {
        float e = B_ENC0[(size_t)t * HD + i];
        B_PE[(size_t)t * HD + i] = e * prec;
        s = fmaf(e, e, s);
    }
    s = block_reduce(s, sred);
    if (tid == 0) B_fe[t] = s * prec;
}

__global__ void __launch_bounds__(NTHR) aux_scal(const float* __restrict__ encprev,
                                                 const float* __restrict__ P,
                                                 const float* __restrict__ qwl,
                                                 const float* __restrict__ qb, int l) {
    __shared__ float sred[NWARP];
    const int t = blockIdx.x, tid = threadIdx.x;
    float d = 0.0f;
    for (int i = tid; i < HD; i += NTHR) {
        float e = encprev[(size_t)t * HD + i] - P[(size_t)t * HD + i];
        d = fmaf(e, qwl[i], d);
    }
    d = block_reduce(d, sred);
    if (tid == 0) B_prec[t] = sigm(d + qb[l]);
}

__global__ void __launch_bounds__(NTHR) aux_pe(const float* __restrict__ enc, int l) {
    __shared__ float sred[NWARP];
    const int t = blockIdx.x, tid = threadIdx.x;
    float prec = B_prec[t], s = 0.0f;
    for (int i = tid; i < HD; i += NTHR) {
        float e = enc[(size_t)t * HD + i];
        B_PE[(size_t)t * HD + i] = e * prec;
        s = fmaf(e, e, s);
    }
    s = block_reduce(s, sred);
    if (tid == 0) B_fe[l * SEQ + t] = s * prec;
}

// ---------------- sequential LSTM chain ----------------------------------
// gates(t) = wih @ (h(t-1) + pe(t)) + (bih+bhh)  [C-GEMM folded in].
// warp gw owns W rows {gw, gw+2HD, gw+3HD} in registers; lane 0 holds all 3
// gate pre-acts of element gw -> computes h(gw), release-publishes ONE float.
// Consumers poll Hout[t-1] with relaxed (coherent) loads, caching valid hits.
__global__ void __launch_bounds__(NTHR, 1) chain_k(const float* __restrict__ Wih,
                                                   const float* __restrict__ PE,
                                                   const float* __restrict__ bih,
                                                   const float* __restrict__ bhh,
                                                   float* __restrict__ Hout) {
    __shared__ __align__(16) float sx[HD];
    const int tid = threadIdx.x, lane = tid & 31, wid = tid >> 5;
    const int gw = blockIdx.x * NWARP + wid;   // 0..1023

    // preload 3 weight rows into registers (one-time read)
    float4 wr0[8], wr1[8], wr2[8];
    {
        const float4* w0 = (const float4*)(Wih + (size_t)gw * HD);
        const float4* w1 = (const float4*)(Wih + (size_t)(gw + 2 * HD) * HD);
        const float4* w2 = (const float4*)(Wih + (size_t)(gw + 3 * HD) * HD);
#pragma unroll
        for (int k = 0; k < 8; k++) {
            wr0[k] = w0[lane + 32 * k];
            wr1[k] = w1[lane + 32 * k];
            wr2[k] = w2[lane + 32 * k];
        }
    }
    // biases are t-invariant: hoisted out of the loop entirely
    float bi = 0.0f, bg = 0.0f, bo = 0.0f;
    if (lane == 0) {
        bi = bih[gw] + bhh[gw];
        bg = bih[gw + 2 * HD] + bhh[gw + 2 * HD];
        bo = bih[gw + 3 * HD] + bhh[gw + 3 * HD];
    }

    for (int t = 0; t < SEQ; t++) {
        // pe(t): independent of the poll -> issued first, latency hidden
        float4 pe = __ldg((const float4*)(PE + (size_t)t * HD) + tid);

        float v0 = 0.0f, v1 = 0.0f, v2 = 0.0f, v3 = 0.0f;
        if (t > 0) {
            const float* src = Hout + (size_t)(t - 1) * HD + tid * 4;
            v0 = ld_relaxed(src + 0); v1 = ld_relaxed(src + 1);
            v2 = ld_relaxed(src + 2); v3 = ld_relaxed(src + 3);
            while (v0 == FLAGF || v1 == FLAGF || v2 == FLAGF || v3 == FLAGF) {
                if (v0 == FLAGF) v0 = ld_relaxed(src + 0);
                if (v1 == FLAGF) v1 = ld_relaxed(src + 1);
                if (v2 == FLAGF) v2 = ld_relaxed(src + 2);
                if (v3 == FLAGF) v3 = ld_relaxed(src + 3);
            }
        }
        sx[tid * 4 + 0] = v0 + pe.x; sx[tid * 4 + 1] = v1 + pe.y;
        sx[tid * 4 + 2] = v2 + pe.z; sx[tid * 4 + 3] = v3 + pe.w;
        __syncthreads();

        float r0 = 0.0f, r1 = 0.0f, r2 = 0.0f;
        const float4* p = (const float4*)sx;
#pragma unroll
        for (int k = 0; k < 8; k++) {
            float4 x = p[lane + 32 * k];
            r0 = fmaf(wr0[k].x, x.x, r0); r0 = fmaf(wr0[k].y, x.y, r0);
            r0 = fmaf(wr0[k].z, x.z, r0); r0 = fmaf(wr0[k].w, x.w, r0);
            r1 = fmaf(wr1[k].x, x.x, r1); r1 = fmaf(wr1[k].y, x.y, r1);
            r1 = fmaf(wr1[k].z, x.z, r1); r1 = fmaf(wr1[k].w, x.w, r1);
            r2 = fmaf(wr2[k].x, x.x, r2); r2 = fmaf(wr2[k].y, x.y, r2);
            r2 = fmaf(wr2[k].z, x.z, r2); r2 = fmaf(wr2[k].w, x.w, r2);
        }
#pragma unroll
        for (int o = 16; o; o >>= 1) {
            r0 += __shfl_xor_sync(0xffffffffu, r0, o);
            r1 += __shfl_xor_sync(0xffffffffu, r1, o);
            r2 += __shfl_xor_sync(0xffffffffu, r2, o);
        }
        if (lane == 0) {
            float hv = sigm(r2 + bo) * tanhf(sigm(r0 + bi) * tanhf(r1 + bg));
            st_release(&Hout[(size_t)t * HD + gw], hv);   // coherent publish
        }
        __syncthreads();    // protect sx before next iteration's overwrite
    }
}

// ---------------- epilogue ----------------
__global__ void __launch_bounds__(NTHR) k_epi(float* __restrict__ out) {
    __shared__ float sred[NWARP];
    const int tid = threadIdx.x;
    const size_t last = (size_t)(SEQ - 1) * HD;
    for (int i = tid; i < HD; i += NTHR) {
        out[i] = 0.0f;                              // pred level 0 == 0
        out[1 * HD + i] = B_P1[last + i];
        out[2 * HD + i] = B_P2[last + i];
        out[3 * HD + i] = B_P3[last + i];
        out[4 * HD + i] = B_ENC0[last + i];         // err level 0 = enc0
        out[5 * HD + i] = B_ENC1[last + i];
        out[6 * HD + i] = B_ENC2[last + i];
        out[7 * HD + i] = B_ENC3[last + i];
    }
    float s = 0.0f;
    for (int t = tid; t < SEQ; t += NTHR)
        s += B_fe[t] + B_fe[SEQ + t] + B_fe[2 * SEQ + t] + B_fe[3 * SEQ + t];
    s = block_reduce(s, sred);
    if (tid == 0) out[8 * HD] = s;
}

// ---------------- launch ----------------
extern "C" void kernel_launch(void* const* d_in, const int* in_sizes, int n_in,
                              void* d_out, int out_size) {
    (void)n_in; (void)out_size;
    const float *obs, *pw1, *pb1, *pw2, *pb2, *ew1, *eb1, *ew2, *eb2;
    const float *qw, *qb, *wih, *bih, *bhh;
    if (in_sizes[0] == SEQ * HD) {
        obs = (const float*)d_in[0];
        pw1 = (const float*)d_in[1];  pb1 = (const float*)d_in[2];
        pw2 = (const float*)d_in[3];  pb2 = (const float*)d_in[4];
        ew1 = (const float*)d_in[5];  eb1 = (const float*)d_in[6];
        ew2 = (const float*)d_in[7];  eb2 = (const float*)d_in[8];
        qw  = (const float*)d_in[9];  qb  = (const float*)d_in[10];
        wih = (const float*)d_in[11];  // whh unused
        bih = (const float*)d_in[13]; bhh = (const float*)d_in[14];
    } else {
        bhh = (const float*)d_in[0];  bih = (const float*)d_in[1];
        eb1 = (const float*)d_in[2];  eb2 = (const float*)d_in[3];
        ew1 = (const float*)d_in[4];  ew2 = (const float*)d_in[5];
        obs = (const float*)d_in[6];
        pb1 = (const float*)d_in[7];  pb2 = (const float*)d_in[8];
        pw1 = (const float*)d_in[9];  pw2 = (const float*)d_in[10];
        qb  = (const float*)d_in[11]; qw  = (const float*)d_in[12];
        wih = (const float*)d_in[14];  // whh unused
    }
    float* out = (float*)d_out;

    float *bG, *bE0, *bE1, *bE2, *bE3, *bP1, *bP2, *bP3, *bH0, *bH1, *bH2, *bPE;
    cudaGetSymbolAddress((void**)&bG,  B_G);
    cudaGetSymbolAddress((void**)&bE0, B_ENC0);
    cudaGetSymbolAddress((void**)&bE1, B_ENC1);
    cudaGetSymbolAddress((void**)&bE2, B_ENC2);
    cudaGetSymbolAddress((void**)&bE3, B_ENC3);
    cudaGetSymbolAddress((void**)&bP1, B_P1);
    cudaGetSymbolAddress((void**)&bP2, B_P2);
    cudaGetSymbolAddress((void**)&bP3, B_P3);
    cudaGetSymbolAddress((void**)&bH0, B_H0);
    cudaGetSymbolAddress((void**)&bH1, B_H1);
    cudaGetSymbolAddress((void**)&bH2, B_H2);
    cudaGetSymbolAddress((void**)&bPE, B_PE);

    float* bH[3]  = {bH0, bH1, bH2};
    float* bEN[4] = {bE0, bE1, bE2, bE3};
    float* bP[4]  = {nullptr, bP1, bP2, bP3};

    const dim3 gg(HD / 32, SEQ / 64);        // (32, 8) = 256 blocks

    // reset h buffers to FLAG (must run every replay, before any chain)
    flag_fill<<<(SEQ * HD + NTHR - 1) / NTHR, NTHR>>>();

    // ---- level 0 precompute ----
    gemm_k<<<gg, 256>>>(ew1, eb1, obs, nullptr, bG, 1);
    gemm_k<<<gg, 256>>>(ew2, eb2, bG, nullptr, bE0, 0);
    lvl0_aux<<<SEQ, NTHR>>>(obs, qw, qb);
    chain_k<<<NBLK, NTHR>>>(wih, bPE, bih, bhh, bH0);

    // ---- levels 1..3 ----
    for (int l = 1; l < NLVL; l++) {
        const float* pw1l = pw1 + (size_t)l * HD * HD;
        const float* pw2l = pw2 + (size_t)l * HD * HD;
        const float* ew1l = ew1 + (size_t)l * HD * HD;
        const float* ew2l = ew2 + (size_t)l * HD * HD;
        const float* wihl = wih + (size_t)l * 4 * HD * HD;

        gemm_k<<<gg, 256>>>(pw1l, pb1 + l * HD, bH[l - 1], nullptr, bG, 1);
        gemm_k<<<gg, 256>>>(pw2l, pb2 + l * HD, bG, nullptr, bP[l], 0);
        aux_scal<<<SEQ, NTHR>>>(bEN[l - 1], bP[l], qw + l * HD, qb, l);
        gemm_k<<<gg, 256>>>(ew1l, eb1 + l * HD, bEN[l - 1], bP[l], bG, 1);
        gemm_k<<<gg, 256>>>(ew2l, eb2 + l * HD, bG, nullptr, bEN[l], 0);
        aux_pe<<<SEQ, NTHR>>>(bEN[l], l);
        if (l < 3) {
            chain_k<<<NBLK, NTHR>>>(wihl, bPE,
                                    bih + (size_t)l * 4 * HD,
                                    bhh + (size_t)l * 4 * HD, bH[l]);
        }
    }
    k_epi<<<1, NTHR>>>(out);
}